// round 1
// baseline (speedup 1.0000x reference)
#include <cuda_runtime.h>

// WeightedLoss: mean over 64M elems of (target==1 ? 1-sigmoid(pred) : 0.1)
// 1 - sigmoid(x) = sigmoid(-x) = 1 / (1 + e^x)
//
// Pure HBM-streaming reduction: 512 MiB read, scalar out.
// Two-pass deterministic reduction (no float atomics).

#define NBLOCKS 2048
#define NTHREADS 256

__device__ float g_partials[NBLOCKS];

__global__ __launch_bounds__(NTHREADS)
void wl_partial_kernel(const float* __restrict__ pred,
                       const int* __restrict__ tgt,
                       int n)
{
    const float4* __restrict__ p4 = reinterpret_cast<const float4*>(pred);
    const int4*   __restrict__ t4 = reinterpret_cast<const int4*>(tgt);
    const int n4 = n >> 2;  // n is divisible by 4 (64M)

    float acc = 0.0f;
    const int stride = gridDim.x * blockDim.x;
    for (int i = blockIdx.x * blockDim.x + threadIdx.x; i < n4; i += stride) {
        float4 p = p4[i];
        int4   t = t4[i];
        // sigmoid(-p) = 1/(1+e^p); __expf overflow -> inf -> __fdividef -> 0 (correct limit)
        float s0 = __fdividef(1.0f, 1.0f + __expf(p.x));
        float s1 = __fdividef(1.0f, 1.0f + __expf(p.y));
        float s2 = __fdividef(1.0f, 1.0f + __expf(p.z));
        float s3 = __fdividef(1.0f, 1.0f + __expf(p.w));
        acc += (t.x == 1) ? s0 : 0.1f;
        acc += (t.y == 1) ? s1 : 0.1f;
        acc += (t.z == 1) ? s2 : 0.1f;
        acc += (t.w == 1) ? s3 : 0.1f;
    }

    // warp reduce
    #pragma unroll
    for (int o = 16; o > 0; o >>= 1)
        acc += __shfl_xor_sync(0xffffffffu, acc, o);

    __shared__ float sw[NTHREADS / 32];
    if ((threadIdx.x & 31) == 0) sw[threadIdx.x >> 5] = acc;
    __syncthreads();

    if (threadIdx.x < 32) {
        float v = (threadIdx.x < NTHREADS / 32) ? sw[threadIdx.x] : 0.0f;
        #pragma unroll
        for (int o = 4; o > 0; o >>= 1)
            v += __shfl_xor_sync(0xffffffffu, v, o);
        if (threadIdx.x == 0) g_partials[blockIdx.x] = v;
    }
}

__global__ __launch_bounds__(1024)
void wl_final_kernel(float* __restrict__ out, float inv_n)
{
    float acc = 0.0f;
    for (int i = threadIdx.x; i < NBLOCKS; i += 1024)
        acc += g_partials[i];

    #pragma unroll
    for (int o = 16; o > 0; o >>= 1)
        acc += __shfl_xor_sync(0xffffffffu, acc, o);

    __shared__ float sw[32];
    if ((threadIdx.x & 31) == 0) sw[threadIdx.x >> 5] = acc;
    __syncthreads();

    if (threadIdx.x < 32) {
        float v = (threadIdx.x < 32) ? sw[threadIdx.x] : 0.0f;
        #pragma unroll
        for (int o = 16; o > 0; o >>= 1)
            v += __shfl_xor_sync(0xffffffffu, v, o);
        if (threadIdx.x == 0) out[0] = v * inv_n;
    }
}

extern "C" void kernel_launch(void* const* d_in, const int* in_sizes, int n_in,
                              void* d_out, int out_size)
{
    const float* pred = (const float*)d_in[0];
    const int*   tgt  = (const int*)d_in[1];
    float*       out  = (float*)d_out;
    const int n = in_sizes[0];

    wl_partial_kernel<<<NBLOCKS, NTHREADS>>>(pred, tgt, n);
    wl_final_kernel<<<1, 1024>>>(out, 1.0f / (float)n);
}